// round 16
// baseline (speedup 1.0000x reference)
#include <cuda_runtime.h>
#include <math.h>

#define cB 64
#define cL 256
#define cE 256
#define cH 512
#define cM 256
#define cHD 64
#define cO 1024
#define cCI 512
#define cTO 768
#define EPS 1e-5f
#define NBLK 128
#define SCRF 6656

typedef unsigned long long ull;

__device__ float g_h[2][cB][cH];
__device__ float g_c[cB][cH];
__device__ float g_ci[cB][cCI];
__device__ float g_outln[2][cB][cTO];
__device__ float g_head[cB][512];
__device__ float g_lnpart[128][cB][2];
__device__ unsigned g_cnt = 0;
__device__ unsigned g_gen = 0;

__device__ __forceinline__ float sigf(float x) { return 1.0f / (1.0f + expf(-x)); }

__device__ __forceinline__ void ffma2(ull& acc, ull a, ull b) {
    asm("fma.rn.f32x2 %0, %1, %2, %0;" : "+l"(acc) : "l"(a), "l"(b));
}
__device__ __forceinline__ float2 unpk(ull v) {
    float2 r;
    asm("mov.b64 {%0, %1}, %2;" : "=f"(r.x), "=f"(r.y) : "l"(v));
    return r;
}

// CG-style grid barrier (no CCTL/L1 flush). Cross-block data via __ldcg/__stcg.
__device__ __forceinline__ void gsync() {
    __syncthreads();
    if (threadIdx.x == 0) {
        unsigned gen;
        asm volatile("ld.relaxed.gpu.global.u32 %0, [%1];" : "=r"(gen) : "l"(&g_gen));
        unsigned prev;
        asm volatile("atom.acq_rel.gpu.global.add.u32 %0, [%1], %2;"
                     : "=r"(prev) : "l"(&g_cnt), "r"(1u) : "memory");
        if (prev == NBLK - 1) {
            asm volatile("st.relaxed.gpu.global.u32 [%0], %1;" :: "l"(&g_cnt), "r"(0u) : "memory");
            asm volatile("st.release.gpu.global.u32 [%0], %1;" :: "l"(&g_gen), "r"(gen + 1u) : "memory");
        } else {
            unsigned cur;
            do {
                asm volatile("ld.acquire.gpu.global.u32 %0, [%1];" : "=r"(cur) : "l"(&g_gen) : "memory");
            } while (cur == gen);
        }
    }
    __syncthreads();
}

// block reductions for 512 threads (16 warps)
__device__ __forceinline__ float brsum(float v, float* red) {
    int tid = threadIdx.x;
#pragma unroll
    for (int o = 16; o; o >>= 1) v += __shfl_xor_sync(0xffffffffu, v, o);
    if ((tid & 31) == 0) red[tid >> 5] = v;
    __syncthreads();
    if (tid == 0) { float s = 0.f; for (int i = 0; i < 16; ++i) s += red[i]; red[0] = s; }
    __syncthreads();
    float r = red[0];
    __syncthreads();
    return r;
}
__device__ __forceinline__ float brmax(float v, float* red) {
    int tid = threadIdx.x;
#pragma unroll
    for (int o = 16; o; o >>= 1) v = fmaxf(v, __shfl_xor_sync(0xffffffffu, v, o));
    if ((tid & 31) == 0) red[tid >> 5] = v;
    __syncthreads();
    if (tid == 0) { float s = red[0]; for (int i = 1; i < 16; ++i) s = fmaxf(s, red[i]); red[0] = s; }
    __syncthreads();
    float r = red[0];
    __syncthreads();
    return r;
}

__device__ __forceinline__ const float* headrow(int g, const float* Wrk, const float* Wwk,
                                                const float* Wws, const float* Wer,
                                                const float* Wad) {
    if (g < 256) return Wrk + (size_t)g * 512;
    if (g < 320) return Wwk + (size_t)(g - 256) * 512;
    if (g == 320) return Wws;
    if (g < 385) return Wer + (size_t)(g - 321) * 512;
    if (g < 449) return Wad + (size_t)(g - 385) * 512;
    return nullptr;
}

// phase A: gates GEMM [64x16, K=1024] split-K across half-blocks, w-dup smem,
// inner loop = LDS.64 + LDS.128 + 2xFFMA2 per 8 FMA. Fused LSTM.
__device__ void doA(int t, float* scr, const float* __restrict__ Wih,
                    const float* __restrict__ Whh, const float* __restrict__ bih,
                    const float* __restrict__ bhh) {
    int tid = threadIdx.x, jj = blockIdx.x;
    int u0 = jj * 4, cur = t & 1, nx = (t + 1) & 1;
    int half = tid >> 8, ltid = tid & 255;
    float* As = scr + half * 2112;          // [32][66] per half
    float* Wd = scr + 4224 + half * 1152;   // [32][36] duplicated pairs per half
    const float* Ab = half ? &g_h[cur][0][0] : &g_ci[0][0];
    const float* Wb = half ? Whh : Wih;
    int mt = ltid >> 3, nt = ltid & 7;
    int am0 = ltid >> 3, ak = (ltid & 7) * 4, am1 = am0 + 32;
    int cp = ltid >> 3, kq = (ltid & 7) * 4;       // W fill: ltid<64
    int ca = 2 * cp, cb = 2 * cp + 1;
    int rowa = (ca >> 2) * 512 + u0 + (ca & 3);
    int rowb = (cb >> 2) * 512 + u0 + (cb & 3);
    ull acc0 = 0ull, acc1 = 0ull;
    float4 va0, va1, vwa, vwb;
    vwa = make_float4(0.f, 0.f, 0.f, 0.f); vwb = vwa;
    va0 = __ldcg((const float4*)(Ab + am0 * 512 + ak));
    va1 = __ldcg((const float4*)(Ab + am1 * 512 + ak));
    if (ltid < 64) {
        vwa = *(const float4*)(Wb + (size_t)rowa * 512 + kq);
        vwb = *(const float4*)(Wb + (size_t)rowb * 512 + kq);
    }
    for (int kt = 0; kt < 512; kt += 32) {
        __syncthreads();
        As[(ak + 0) * 66 + am0] = va0.x; As[(ak + 1) * 66 + am0] = va0.y;
        As[(ak + 2) * 66 + am0] = va0.z; As[(ak + 3) * 66 + am0] = va0.w;
        As[(ak + 0) * 66 + am1] = va1.x; As[(ak + 1) * 66 + am1] = va1.y;
        As[(ak + 2) * 66 + am1] = va1.z; As[(ak + 3) * 66 + am1] = va1.w;
        if (ltid < 64) {
            *(float4*)&Wd[(kq + 0) * 36 + 4 * cp] = make_float4(vwa.x, vwa.x, vwb.x, vwb.x);
            *(float4*)&Wd[(kq + 1) * 36 + 4 * cp] = make_float4(vwa.y, vwa.y, vwb.y, vwb.y);
            *(float4*)&Wd[(kq + 2) * 36 + 4 * cp] = make_float4(vwa.z, vwa.z, vwb.z, vwb.z);
            *(float4*)&Wd[(kq + 3) * 36 + 4 * cp] = make_float4(vwa.w, vwa.w, vwb.w, vwb.w);
        }
        if (kt + 32 < 512) {
            va0 = __ldcg((const float4*)(Ab + am0 * 512 + kt + 32 + ak));
            va1 = __ldcg((const float4*)(Ab + am1 * 512 + kt + 32 + ak));
            if (ltid < 64) {
                vwa = *(const float4*)(Wb + (size_t)rowa * 512 + kt + 32 + kq);
                vwb = *(const float4*)(Wb + (size_t)rowb * 512 + kt + 32 + kq);
            }
        }
        __syncthreads();
#pragma unroll
        for (int k = 0; k < 32; ++k) {
            ull a = *(const ull*)&As[k * 66 + mt * 2];
            ulonglong2 w = *(const ulonglong2*)&Wd[k * 36 + 4 * nt];
            ffma2(acc0, a, w.x);
            ffma2(acc1, a, w.y);
        }
    }
    __syncthreads();
    float* P1 = scr;          // 1024 (half1 partials)
    float* Cs = scr + 1024;   // [16][66]
    float* Ps = scr + 2112;   // 256
    if (half == 1) {
        float2 r0 = unpk(acc0), r1 = unpk(acc1);
        *(float4*)&P1[ltid * 4] = make_float4(r0.x, r0.y, r1.x, r1.y);
    }
    __syncthreads();
    if (half == 0) {
        float4 o = *(const float4*)&P1[ltid * 4];
        float2 r0 = unpk(acc0), r1 = unpk(acc1);
        Cs[(2 * nt) * 66 + 2 * mt] = r0.x + o.x;
        Cs[(2 * nt) * 66 + 2 * mt + 1] = r0.y + o.y;
        Cs[(2 * nt + 1) * 66 + 2 * mt] = r1.x + o.z;
        Cs[(2 * nt + 1) * 66 + 2 * mt + 1] = r1.y + o.w;
    }
    __syncthreads();
    if (tid < 256) {
        int m = tid & 63, u = tid >> 6;
        int U = u0 + u;
        float gi = Cs[(u) * 66 + m]      + bih[U]        + bhh[U];
        float gf = Cs[(4 + u) * 66 + m]  + bih[512 + U]  + bhh[512 + U];
        float gg = Cs[(8 + u) * 66 + m]  + bih[1024 + U] + bhh[1024 + U];
        float go = Cs[(12 + u) * 66 + m] + bih[1536 + U] + bhh[1536 + U];
        float cc = sigf(gf) * g_c[m][U] + sigf(gi) * tanhf(gg);
        float hh = sigf(go) * tanhf(cc);
        g_c[m][U] = cc;
        __stcg(&g_h[nx][m][U], hh);
        Ps[u * 64 + m] = hh;
    }
    __syncthreads();
    if (tid < 64) {
        float h0 = Ps[tid], h1 = Ps[64 + tid], h2 = Ps[128 + tid], h3 = Ps[192 + tid];
        __stcg(&g_lnpart[jj][tid][0], h0 + h1 + h2 + h3);
        __stcg(&g_lnpart[jj][tid][1], h0 * h0 + h1 * h1 + h2 * h2 + h3 * h3);
    }
}

// phase B: heads GEMM, 4 cols/block, K split 2x256, LN(h) inline
__device__ void doHeads(int q, int nx, float* scr,
                        const float* __restrict__ lnhg, const float* __restrict__ lnhb,
                        const float* __restrict__ Wrk, const float* __restrict__ Wwk,
                        const float* __restrict__ Wws, const float* __restrict__ Wer,
                        const float* __restrict__ Wad) {
    int tid = threadIdx.x;
    int half = tid >> 8, ltid = tid & 255;
    float* As = scr + half * 2112;         // [32][66]
    float* Ws = scr + 4224 + half * 128;   // [32][4]
    float* smean = scr + 4480;             // 64
    float* srstd = scr + 4544;             // 64
    float* hacc = scr + 4608;              // 512
    if (tid < 64) {
        float s = 0.f, s2 = 0.f;
#pragma unroll 8
        for (int j = 0; j < 128; ++j) {
            float2 lp = __ldcg((const float2*)&g_lnpart[j][tid][0]);
            s += lp.x; s2 += lp.y;
        }
        float m = s * (1.f / 512);
        smean[tid] = m;
        srstd[tid] = rsqrtf(s2 * (1.f / 512) - m * m + EPS);
    }
    __syncthreads();
    int m = ltid >> 2, c = ltid & 3;
    int ar0 = ltid >> 3, ar1 = ar0 + 32, ak = (ltid & 7) * 4;
    int kb = half * 256;
    const float* wp = headrow(q * 4 + (ltid >> 3), Wrk, Wwk, Wws, Wer, Wad);  // ltid<32
    float acc = 0.f;
    float4 hv0, hv1, gv0, bv0, vwh = make_float4(0.f, 0.f, 0.f, 0.f);
    hv0 = __ldcg((const float4*)&g_h[nx][ar0][kb + ak]);
    hv1 = __ldcg((const float4*)&g_h[nx][ar1][kb + ak]);
    gv0 = *(const float4*)&lnhg[kb + ak];
    bv0 = *(const float4*)&lnhb[kb + ak];
    if (ltid < 32 && wp) vwh = *(const float4*)(wp + kb + ((ltid & 7) * 4));
    for (int kt = 0; kt < 256; kt += 32) {
        __syncthreads();
        {
            float mm = smean[ar0], rs = srstd[ar0];
            As[(ak + 0) * 66 + ar0] = (hv0.x - mm) * rs * gv0.x + bv0.x;
            As[(ak + 1) * 66 + ar0] = (hv0.y - mm) * rs * gv0.y + bv0.y;
            As[(ak + 2) * 66 + ar0] = (hv0.z - mm) * rs * gv0.z + bv0.z;
            As[(ak + 3) * 66 + ar0] = (hv0.w - mm) * rs * gv0.w + bv0.w;
            mm = smean[ar1]; rs = srstd[ar1];
            As[(ak + 0) * 66 + ar1] = (hv1.x - mm) * rs * gv0.x + bv0.x;
            As[(ak + 1) * 66 + ar1] = (hv1.y - mm) * rs * gv0.y + bv0.y;
            As[(ak + 2) * 66 + ar1] = (hv1.z - mm) * rs * gv0.z + bv0.z;
            As[(ak + 3) * 66 + ar1] = (hv1.w - mm) * rs * gv0.w + bv0.w;
        }
        if (ltid < 32) {
            int c2 = ltid >> 3, kq = (ltid & 7) * 4;
            Ws[(kq + 0) * 4 + c2] = vwh.x; Ws[(kq + 1) * 4 + c2] = vwh.y;
            Ws[(kq + 2) * 4 + c2] = vwh.z; Ws[(kq + 3) * 4 + c2] = vwh.w;
        }
        if (kt + 32 < 256) {
            hv0 = __ldcg((const float4*)&g_h[nx][ar0][kb + kt + 32 + ak]);
            hv1 = __ldcg((const float4*)&g_h[nx][ar1][kb + kt + 32 + ak]);
            gv0 = *(const float4*)&lnhg[kb + kt + 32 + ak];
            bv0 = *(const float4*)&lnhb[kb + kt + 32 + ak];
            if (ltid < 32 && wp) vwh = *(const float4*)(wp + kb + kt + 32 + ((ltid & 7) * 4));
        }
        __syncthreads();
#pragma unroll
        for (int k = 0; k < 32; ++k) acc += As[k * 66 + m] * Ws[k * 4 + c];
    }
    hacc[tid] = acc;
    __syncthreads();
    if (tid < 256) __stcg(&g_head[m][q * 4 + c], hacc[tid] + hacc[tid + 256]);
}

// phase C (blocks 64..127): proj, 16 cols/block, K split 2x384, w-dup + FFMA2
__device__ void doProj(int p, int trow, float* scr, const float* __restrict__ Aouts,
                       const float* __restrict__ Wproj, const float* __restrict__ bproj,
                       float* __restrict__ out) {
    int tid = threadIdx.x;
    int half = tid >> 8, ltid = tid & 255;
    float* As = scr + half * 2176;          // [32][68]
    float* Wd = scr + 4352 + half * 1024;   // [32][32] duplicated pairs
    float* pacc = scr + 6400;               // wait: need <= SCRF; see layout note
    // layout: As 2x2176=4352, Wd 2x1024=2048 -> 6400, pacc 1024 -> 7424 > SCRF?
    // use pacc overlapping As of half 0 after compute instead:
    pacc = scr;  // reuse As half0 region after inner loops complete (guarded by syncs)
    int r0 = (ltid >> 3) * 2, c0 = (ltid & 7) * 2;
    int ar0 = ltid >> 3, ar1 = ar0 + 32, ak = (ltid & 7) * 4;
    int cp = ltid >> 3, kq = (ltid & 7) * 4;  // W fill: ltid<64
    int kb = half * 384;
    ull acc0 = 0ull, acc1 = 0ull;  // acc0={r0c0,r1c0}, acc1={r0c1,r1c1}
    float4 va0, va1, vwa, vwb;
    vwa = make_float4(0.f, 0.f, 0.f, 0.f); vwb = vwa;
    va0 = __ldcg((const float4*)&Aouts[ar0 * 768 + kb + ak]);
    va1 = __ldcg((const float4*)&Aouts[ar1 * 768 + kb + ak]);
    if (ltid < 64) {
        vwa = *(const float4*)&Wproj[(size_t)(16 * p + 2 * cp) * 768 + kb + kq];
        vwb = *(const float4*)&Wproj[(size_t)(16 * p + 2 * cp + 1) * 768 + kb + kq];
    }
    for (int kt = 0; kt < 384; kt += 32) {
        __syncthreads();
        As[(ak + 0) * 68 + ar0] = va0.x; As[(ak + 1) * 68 + ar0] = va0.y;
        As[(ak + 2) * 68 + ar0] = va0.z; As[(ak + 3) * 68 + ar0] = va0.w;
        As[(ak + 0) * 68 + ar1] = va1.x; As[(ak + 1) * 68 + ar1] = va1.y;
        As[(ak + 2) * 68 + ar1] = va1.z; As[(ak + 3) * 68 + ar1] = va1.w;
        if (ltid < 64) {
            float* wd = scr + 4352 + half * 1024;
            *(float4*)&wd[(kq + 0) * 32 + 4 * cp] = make_float4(vwa.x, vwa.x, vwb.x, vwb.x);
            *(float4*)&wd[(kq + 1) * 32 + 4 * cp] = make_float4(vwa.y, vwa.y, vwb.y, vwb.y);
            *(float4*)&wd[(kq + 2) * 32 + 4 * cp] = make_float4(vwa.z, vwa.z, vwb.z, vwb.z);
            *(float4*)&wd[(kq + 3) * 32 + 4 * cp] = make_float4(vwa.w, vwa.w, vwb.w, vwb.w);
        }
        if (kt + 32 < 384) {
            va0 = __ldcg((const float4*)&Aouts[ar0 * 768 + kb + kt + 32 + ak]);
            va1 = __ldcg((const float4*)&Aouts[ar1 * 768 + kb + kt + 32 + ak]);
            if (ltid < 64) {
                vwa = *(const float4*)&Wproj[(size_t)(16 * p + 2 * cp) * 768 + kb + kt + 32 + kq];
                vwb = *(const float4*)&Wproj[(size_t)(16 * p + 2 * cp + 1) * 768 + kb + kt + 32 + kq];
            }
        }
        __syncthreads();
        {
            const float* wd = scr + 4352 + half * 1024;
#pragma unroll
            for (int k = 0; k < 32; ++k) {
                ull a = *(const ull*)&As[k * 68 + r0];
                ulonglong2 w = *(const ulonglong2*)&wd[k * 32 + 4 * (ltid & 7)];
                ffma2(acc0, a, w.x);
                ffma2(acc1, a, w.y);
            }
        }
    }
    __syncthreads();
    if (half == 1) {
        float2 q0 = unpk(acc0), q1 = unpk(acc1);
        *(float4*)&pacc[ltid * 4] = make_float4(q0.x, q0.y, q1.x, q1.y);
    }
    __syncthreads();
    if (half == 0) {
        float4 o = *(const float4*)&pacc[ltid * 4];
        float2 q0 = unpk(acc0), q1 = unpk(acc1);
        int col = 16 * p + c0;
        float b0 = bproj[col], b1 = bproj[col + 1];
        out[((size_t)(r0 + 0) * cL + trow) * cO + col]     = q0.x + o.x + b0;
        out[((size_t)(r0 + 0) * cL + trow) * cO + col + 1] = q1.x + o.z + b1;
        out[((size_t)(r0 + 1) * cL + trow) * cO + col]     = q0.y + o.y + b0;
        out[((size_t)(r0 + 1) * cL + trow) * cO + col + 1] = q1.y + o.w + b1;
    }
}

// phase C (blocks 0..63): memory write/read + outln + next ci (512 threads)
__device__ void doMem(int t, int b, float* s_mem, float* scr, const float* __restrict__ x,
                      const float* __restrict__ brk, const float* __restrict__ bwk,
                      const float* __restrict__ bws, const float* __restrict__ ber,
                      const float* __restrict__ bad,
                      const float* __restrict__ lnhg, const float* __restrict__ lnhb,
                      const float* __restrict__ lnrkg, const float* __restrict__ lnrkb,
                      const float* __restrict__ lnwkg, const float* __restrict__ lnwkb,
                      const float* __restrict__ lnmg, const float* __restrict__ lnmb,
                      const float* __restrict__ lnog, const float* __restrict__ lnob,
                      const float* __restrict__ lning, const float* __restrict__ lninb) {
    float* s_hn = scr;           // 512
    float* s_rk = scr + 512;     // 256
    float* s_wk = scr + 768;     // 64
    float* s_er = scr + 832;     // 64
    float* s_ad = scr + 896;     // 64
    float* s_wkln = scr + 960;   // 64
    float* s_rkln = scr + 1024;  // 256
    float* s_wsc = scr + 1280;   // 256
    float* s_rsc = scr + 1536;   // 1024
    float* s_rv = scr + 2560;    // 256
    float* s_rvp = scr + 2816;   // 512
    float* red = scr + 3328;     // 16
    float* misc = scr + 3344;    // 4
    int tid = threadIdx.x, warp = tid >> 5, lane = tid & 31;
    int nx = (t + 1) & 1, ob = t & 1;

    if (tid < 32) {
        float s = 0.f, s2 = 0.f;
#pragma unroll
        for (int j = 0; j < 4; ++j) {
            float2 lp = __ldcg((const float2*)&g_lnpart[lane * 4 + j][b][0]);
            s += lp.x; s2 += lp.y;
        }
#pragma unroll
        for (int o = 16; o; o >>= 1) {
            s += __shfl_xor_sync(0xffffffffu, s, o);
            s2 += __shfl_xor_sync(0xffffffffu, s2, o);
        }
        if (tid == 0) {
            float m = s * (1.f / 512);
            misc[1] = m;
            misc[2] = rsqrtf(s2 * (1.f / 512) - m * m + EPS);
        }
    }
    __syncthreads();
    float hm = misc[1], hrs = misc[2];
    s_hn[tid] = (__ldcg(&g_h[nx][b][tid]) - hm) * hrs * lnhg[tid] + lnhb[tid];
    if (tid < 449) {
        float v = __ldcg(&g_head[b][tid]);
        if (tid < 256) s_rk[tid] = v + brk[tid];
        else if (tid < 320) s_wk[tid - 256] = v + bwk[tid - 256];
        else if (tid == 320) misc[0] = sigf(v + bws[0]);
        else if (tid < 385) s_er[tid - 321] = sigf(v + ber[tid - 321]);
        else s_ad[tid - 385] = tanhf(v + bad[tid - 385]);
    }
    __syncthreads();
    if (warp == 0) {
        float x0 = s_wk[lane], x1 = s_wk[lane + 32], s = x0 + x1;
#pragma unroll
        for (int o = 16; o; o >>= 1) s += __shfl_xor_sync(0xffffffffu, s, o);
        float mean = s * (1.f / 64), d0 = x0 - mean, d1 = x1 - mean;
        float vs = d0 * d0 + d1 * d1;
#pragma unroll
        for (int o = 16; o; o >>= 1) vs += __shfl_xor_sync(0xffffffffu, vs, o);
        float rs = rsqrtf(vs * (1.f / 64) + EPS);
        s_wkln[lane] = d0 * rs * lnwkg[lane] + lnwkb[lane];
        s_wkln[lane + 32] = d1 * rs * lnwkg[lane + 32] + lnwkb[lane + 32];
    } else if (warp <= 4) {
        int r = warp - 1;
        float x0 = s_rk[r * 64 + lane], x1 = s_rk[r * 64 + lane + 32], s = x0 + x1;
#pragma unroll
        for (int o = 16; o; o >>= 1) s += __shfl_xor_sync(0xffffffffu, s, o);
        float mean = s * (1.f / 64), d0 = x0 - mean, d1 = x1 - mean;
        float vs = d0 * d0 + d1 * d1;
#pragma unroll
        for (int o = 16; o; o >>= 1) vs += __shfl_xor_sync(0xffffffffu, vs, o);
        float rs = rsqrtf(vs * (1.f / 64) + EPS);
        s_rkln[r * 64 + lane] = d0 * rs * lnrkg[lane] + lnrkb[lane];
        s_rkln[r * 64 + lane + 32] = d1 * rs * lnrkg[lane + 32] + lnrkb[lane + 32];
    }
    __syncthreads();
    float mg0 = lnmg[lane], mg1 = lnmg[lane + 32];
    float mb0 = lnmb[lane], mb1 = lnmb[lane + 32];
    float wkl0 = s_wkln[lane], wkl1 = s_wkln[lane + 32];
    for (int m = warp; m < cM; m += 16) {
        float x0 = s_mem[m * 64 + lane], x1 = s_mem[m * 64 + lane + 32], s = x0 + x1;
#pragma unroll
        for (int o = 16; o; o >>= 1) s += __shfl_xor_sync(0xffffffffu, s, o);
        float mean = s * (1.f / 64), d0 = x0 - mean, d1 = x1 - mean;
        float vs = d0 * d0 + d1 * d1;
#pragma unroll
        for (int o = 16; o; o >>= 1) vs += __shfl_xor_sync(0xffffffffu, vs, o);
        float rs = rsqrtf(vs * (1.f / 64) + EPS);
        float dot = (d0 * rs * mg0 + mb0) * wkl0 + (d1 * rs * mg1 + mb1) * wkl1;
#pragma unroll
        for (int o = 16; o; o >>= 1) dot += __shfl_xor_sync(0xffffffffu, dot, o);
        if (lane == 0) s_wsc[m] = dot;
    }
    __syncthreads();
    {
        float v = (tid < 256) ? s_wsc[tid] : -3e38f;
        float mx = brmax(v, red);
        float e = (tid < 256) ? expf(v - mx) : 0.f;
        float su = brsum(e, red);
        if (tid < 256) s_wsc[tid] = e / su * misc[0];
    }
    __syncthreads();
    for (int i = tid; i < cM * cHD; i += 512) {
        int m = i >> 6, hh = i & 63;
        float w = s_wsc[m];
        s_mem[i] = s_mem[i] * (1.f - w * s_er[hh]) + w * s_ad[hh];
    }
    __syncthreads();
    for (int m = warp; m < cM; m += 16) {
        float x0 = s_mem[m * 64 + lane], x1 = s_mem[m * 64 + lane + 32], s = x0 + x1;
#pragma unroll
        for (int o = 16; o; o >>= 1) s += __shfl_xor_sync(0xffffffffu, s, o);
        float mean = s * (1.f / 64), d0 = x0 - mean, d1 = x1 - mean;
        float vs = d0 * d0 + d1 * d1;
#pragma unroll
        for (int o = 16; o; o >>= 1) vs += __shfl_xor_sync(0xffffffffu, vs, o);
        float rs = rsqrtf(vs * (1.f / 64) + EPS);
        float n0 = d0 * rs * mg0 + mb0, n1 = d1 * rs * mg1 + mb1;
#pragma unroll
        for (int r = 0; r < 4; ++r) {
            float a = n0 * s_rkln[r * 64 + lane] + n1 * s_rkln[r * 64 + lane + 32];
#pragma unroll
            for (int o = 16; o; o >>= 1) a += __shfl_xor_sync(0xffffffffu, a, o);
            if (lane == 0) s_rsc[r * 256 + m] = a;
        }
    }
    __syncthreads();
#pragma unroll
    for (int r = 0; r < 4; ++r) {
        float v = (tid < 256) ? s_rsc[r * 256 + tid] : -3e38f;
        float mx = brmax(v, red);
        float e = (tid < 256) ? expf(v - mx) : 0.f;
        float su = brsum(e, red);
        if (tid < 256) s_rsc[r * 256 + tid] = e / su;
    }
    __syncthreads();
    {
        int r = tid >> 7, rest = tid & 127, hf = rest >> 6, hh = rest & 63;
        int mb = hf * 128;
        float a0 = 0.f, a1 = 0.f, a2 = 0.f, a3 = 0.f;
#pragma unroll 4
        for (int m = 0; m < 128; m += 4) {
            a0 += s_rsc[r * 256 + mb + m + 0] * s_mem[(mb + m + 0) * 64 + hh];
            a1 += s_rsc[r * 256 + mb + m + 1] * s_mem[(mb + m + 1) * 64 + hh];
            a2 += s_rsc[r * 256 + mb + m + 2] * s_mem[(mb + m + 2) * 64 + hh];
            a3 += s_rsc[r * 256 + mb + m + 3] * s_mem[(mb + m + 3) * 64 + hh];
        }
        s_rvp[tid] = (a0 + a1) + (a2 + a3);
    }
    __syncthreads();
    if (tid < 256) {
        int r = tid >> 6, hh = tid & 63;
        s_rv[tid] = s_rvp[r * 128 + hh] + s_rvp[r * 128 + 64 + hh];
    }
    __syncthreads();
    {
        float o0 = s_hn[tid];
        float o2 = (tid < 256) ? s_rv[tid] : 0.f;
        float mean = brsum(o0 + o2, red) * (1.f / cTO);
        float d0 = o0 - mean, d2 = o2 - mean;
        float var = brsum(d0 * d0 + ((tid < 256) ? d2 * d2 : 0.f), red) * (1.f / cTO);
        float rs = rsqrtf(var + EPS);
        __stcg(&g_outln[ob][b][tid], d0 * rs * lnog[tid] + lnob[tid]);
        if (tid < 256)
            __stcg(&g_outln[ob][b][512 + tid], d2 * rs * lnog[512 + tid] + lnob[512 + tid]);
    }
    if (t + 1 < cL) {
        const float* xn = x + ((size_t)b * cL + t + 1) * cE;
        float a = (tid < 256) ? xn[tid] : s_rv[tid - 256];
        float mean = brsum(a, red) * (1.f / cCI);
        float d = a - mean;
        float var = brsum(d * d, red) * (1.f / cCI);
        float rs = rsqrtf(var + EPS);
        __stcg(&g_ci[b][tid], d * rs * lning[tid] + lninb[tid]);
    }
}

__global__ void __launch_bounds__(512, 1) k_persist(
    const float* __restrict__ x, const float* __restrict__ Wih,
    const float* __restrict__ Whh, const float* __restrict__ bih,
    const float* __restrict__ bhh, const float* __restrict__ lning,
    const float* __restrict__ lninb, const float* __restrict__ lnhg,
    const float* __restrict__ lnhb, const float* __restrict__ Wrk,
    const float* __restrict__ brk, const float* __restrict__ Wwk,
    const float* __restrict__ bwk, const float* __restrict__ Wws,
    const float* __restrict__ bws, const float* __restrict__ Wer,
    const float* __restrict__ ber, const float* __restrict__ Wad,
    const float* __restrict__ bad, const float* __restrict__ lnrkg,
    const float* __restrict__ lnrkb, const float* __restrict__ lnwkg,
    const float* __restrict__ lnwkb, const float* __restrict__ lnmg,
    const float* __restrict__ lnmb, const float* __restrict__ lnog,
    const float* __restrict__ lnob, const float* __restrict__ Wproj,
    const float* __restrict__ bproj, float* __restrict__ out,
    float* __restrict__ memg, float* __restrict__ hout, float* __restrict__ cout) {
    extern __shared__ float sm[];
    float* s_mem = sm;          // 16384 (persistent memory, blocks 0..63)
    float* scr = sm + 16384;    // SCRF scratch
    int bx = blockIdx.x, tid = threadIdx.x;

    if (bx < 64) {
        for (int i = tid; i < cM * cHD; i += 512) s_mem[i] = 0.f;
        int b = bx;
        g_c[b][tid] = 0.f;
        __stcg(&g_h[0][b][tid], 0.f);
        float* red = scr;
        float a = (tid < 256) ? x[(size_t)b * cL * cE + tid] : 0.f;
        float mean = brsum(a, red) * (1.f / cCI);
        float d = a - mean;
        float var = brsum(d * d, red) * (1.f / cCI);
        float rs = rsqrtf(var + EPS);
        __stcg(&g_ci[b][tid], d * rs * lning[tid] + lninb[tid]);
    }
    gsync();

    for (int t = 0; t < cL; ++t) {
        doA(t, scr, Wih, Whh, bih, bhh);
        gsync();
        doHeads(bx, (t + 1) & 1, scr, lnhg, lnhb, Wrk, Wwk, Wws, Wer, Wad);
        gsync();
        if (bx < 64) {
            doMem(t, bx, s_mem, scr, x, brk, bwk, bws, ber, bad, lnhg, lnhb,
                  lnrkg, lnrkb, lnwkg, lnwkb, lnmg, lnmb, lnog, lnob, lning, lninb);
        } else if (t > 0) {
            doProj(bx - 64, t - 1, scr, &g_outln[(t - 1) & 1][0][0], Wproj, bproj, out);
        }
        gsync();
    }
    if (bx >= 64) {
        doProj(bx - 64, cL - 1, scr, &g_outln[(cL - 1) & 1][0][0], Wproj, bproj, out);
    } else {
        int b = bx;
        for (int i = tid; i < cM * cHD; i += 512) memg[(size_t)b * cM * cHD + i] = s_mem[i];
        hout[b * cH + tid] = __ldcg(&g_h[0][b][tid]);
        cout[b * cH + tid] = __ldcg(&g_c[b][tid]);
    }
}

extern "C" void kernel_launch(void* const* d_in, const int* in_sizes, int n_in,
                              void* d_out, int out_size) {
    const float** p = (const float**)d_in;
    float* out = (float*)d_out;
    float* memg = out + (size_t)cB * cL * cO;
    float* hout = memg + (size_t)cB * cM * cHD;
    float* cout = hout + (size_t)cB * cH;
    const int smem = (16384 + SCRF) * 4;
    cudaFuncSetAttribute(k_persist, cudaFuncAttributeMaxDynamicSharedMemorySize, smem);
    k_persist<<<NBLK, 512, smem>>>(p[0], p[1], p[2], p[3], p[4], p[5], p[6], p[7], p[8],
                                   p[9], p[10], p[11], p[12], p[13], p[14], p[15], p[16],
                                   p[17], p[18], p[19], p[20], p[21], p[22], p[23], p[24],
                                   p[25], p[26], p[27], p[28], out, memg, hout, cout);
}

// round 17
// speedup vs baseline: 1.2245x; 1.2245x over previous
#include <cuda_runtime.h>
#include <math.h>

#define cB 64
#define cL 256
#define cE 256
#define cH 512
#define cM 256
#define cHD 64
#define cO 1024
#define cCI 512
#define cTO 768
#define EPS 1e-5f
#define NBLK 128
#define NTHR 1024
#define SCRF 11520

typedef unsigned long long ull;

__device__ float g_h[2][cB][cH];
__device__ float g_c[cB][cH];
__device__ float g_ci[cB][cCI];
__device__ float g_outln[2][cB][cTO];
__device__ float g_head[cB][512];
__device__ float g_lnpart[128][cB][2];
__device__ unsigned g_cnt = 0;
__device__ unsigned g_gen = 0;

__device__ __forceinline__ float sigf(float x) { return 1.0f / (1.0f + expf(-x)); }

__device__ __forceinline__ ull dup2(float w) {
    ull r;
    asm("mov.b64 %0, {%1, %1};" : "=l"(r) : "f"(w));
    return r;
}
__device__ __forceinline__ void ffma2(ull& acc, ull a, ull b) {
    asm("fma.rn.f32x2 %0, %1, %2, %0;" : "+l"(acc) : "l"(a), "l"(b));
}
__device__ __forceinline__ float2 unpk(ull v) {
    float2 r;
    asm("mov.b64 {%0, %1}, %2;" : "=f"(r.x), "=f"(r.y) : "l"(v));
    return r;
}

// CG-style grid barrier (no CCTL/L1 flush). Cross-block data via __ldcg/__stcg.
__device__ __forceinline__ void gsync() {
    __syncthreads();
    if (threadIdx.x == 0) {
        unsigned gen;
        asm volatile("ld.relaxed.gpu.global.u32 %0, [%1];" : "=r"(gen) : "l"(&g_gen));
        unsigned prev;
        asm volatile("atom.acq_rel.gpu.global.add.u32 %0, [%1], %2;"
                     : "=r"(prev) : "l"(&g_cnt), "r"(1u) : "memory");
        if (prev == NBLK - 1) {
            asm volatile("st.relaxed.gpu.global.u32 [%0], %1;" :: "l"(&g_cnt), "r"(0u) : "memory");
            asm volatile("st.release.gpu.global.u32 [%0], %1;" :: "l"(&g_gen), "r"(gen + 1u) : "memory");
        } else {
            unsigned cur;
            do {
                asm volatile("ld.acquire.gpu.global.u32 %0, [%1];" : "=r"(cur) : "l"(&g_gen) : "memory");
            } while (cur == gen);
        }
    }
    __syncthreads();
}

// block reductions for 1024 threads (32 warps)
__device__ __forceinline__ float brsum(float v, float* red) {
    int tid = threadIdx.x;
#pragma unroll
    for (int o = 16; o; o >>= 1) v += __shfl_xor_sync(0xffffffffu, v, o);
    if ((tid & 31) == 0) red[tid >> 5] = v;
    __syncthreads();
    if (tid == 0) { float s = 0.f; for (int i = 0; i < 32; ++i) s += red[i]; red[0] = s; }
    __syncthreads();
    float r = red[0];
    __syncthreads();
    return r;
}
__device__ __forceinline__ float brmax(float v, float* red) {
    int tid = threadIdx.x;
#pragma unroll
    for (int o = 16; o; o >>= 1) v = fmaxf(v, __shfl_xor_sync(0xffffffffu, v, o));
    if ((tid & 31) == 0) red[tid >> 5] = v;
    __syncthreads();
    if (tid == 0) { float s = red[0]; for (int i = 1; i < 32; ++i) s = fmaxf(s, red[i]); red[0] = s; }
    __syncthreads();
    float r = red[0];
    __syncthreads();
    return r;
}

__device__ __forceinline__ const float* headrow(int g, const float* Wrk, const float* Wwk,
                                                const float* Wws, const float* Wer,
                                                const float* Wad) {
    if (g < 256) return Wrk + (size_t)g * 512;
    if (g < 320) return Wwk + (size_t)(g - 256) * 512;
    if (g == 320) return Wws;
    if (g < 385) return Wer + (size_t)(g - 321) * 512;
    if (g < 449) return Wad + (size_t)(g - 385) * 512;
    return nullptr;
}

// phase A: gates GEMM [64x16, K=1024], 4-way split-K (quarters), fused LSTM
__device__ void doA(int t, float* scr, const float* __restrict__ Wih,
                    const float* __restrict__ Whh, const float* __restrict__ bih,
                    const float* __restrict__ bhh) {
    int tid = threadIdx.x, jj = blockIdx.x;
    int u0 = jj * 4, cur = t & 1, nx = (t + 1) & 1;
    int q = tid >> 8, ltid = tid & 255;
    float* As = scr + q * 2624;      // [32][66]
    float* Ws = As + 2112;           // [32][16]
    const float* Ab = (q < 2) ? &g_ci[0][0] + q * 256 : &g_h[cur][0][0] + (q - 2) * 256;
    const float* Wb = (q < 2) ? Wih + q * 256 : Whh + (q - 2) * 256;
    int mt = ltid >> 3, nt = ltid & 7;
    int am0 = ltid >> 3, ak = (ltid & 7) * 4, am1 = am0 + 32;
    int wc = ltid >> 3, wk = (ltid & 7) * 4;
    int wrow = (wc >> 2) * 512 + u0 + (wc & 3);
    ull acc0 = 0ull, acc1 = 0ull;
    float4 va0, va1, vw = make_float4(0.f, 0.f, 0.f, 0.f);
    va0 = __ldcg((const float4*)(Ab + am0 * 512 + ak));
    va1 = __ldcg((const float4*)(Ab + am1 * 512 + ak));
    if (ltid < 128) vw = *(const float4*)(Wb + (size_t)wrow * 512 + wk);
    for (int kt = 0; kt < 256; kt += 32) {
        __syncthreads();
        As[(ak + 0) * 66 + am0] = va0.x; As[(ak + 1) * 66 + am0] = va0.y;
        As[(ak + 2) * 66 + am0] = va0.z; As[(ak + 3) * 66 + am0] = va0.w;
        As[(ak + 0) * 66 + am1] = va1.x; As[(ak + 1) * 66 + am1] = va1.y;
        As[(ak + 2) * 66 + am1] = va1.z; As[(ak + 3) * 66 + am1] = va1.w;
        if (ltid < 128) {
            Ws[(wk + 0) * 16 + wc] = vw.x; Ws[(wk + 1) * 16 + wc] = vw.y;
            Ws[(wk + 2) * 16 + wc] = vw.z; Ws[(wk + 3) * 16 + wc] = vw.w;
        }
        if (kt + 32 < 256) {
            va0 = __ldcg((const float4*)(Ab + am0 * 512 + kt + 32 + ak));
            va1 = __ldcg((const float4*)(Ab + am1 * 512 + kt + 32 + ak));
            if (ltid < 128) vw = *(const float4*)(Wb + (size_t)wrow * 512 + kt + 32 + wk);
        }
        __syncthreads();
#pragma unroll
        for (int k = 0; k < 32; ++k) {
            ull a = *(const ull*)&As[k * 66 + mt * 2];
            float2 w = *(const float2*)&Ws[k * 16 + nt * 2];
            ffma2(acc0, a, dup2(w.x));
            ffma2(acc1, a, dup2(w.y));
        }
    }
    __syncthreads();
    float* P = scr;           // 3072 (quarters 1..3 partials)
    float* Cs = scr + 3072;   // [16][66]
    float* Ps = scr + 4128;   // 256
    if (q > 0) {
        float2 r0 = unpk(acc0), r1 = unpk(acc1);
        *(float4*)&P[(q - 1) * 1024 + ltid * 4] = make_float4(r0.x, r0.y, r1.x, r1.y);
    }
    __syncthreads();
    if (q == 0) {
        float4 o1 = *(const float4*)&P[ltid * 4];
        float4 o2 = *(const float4*)&P[1024 + ltid * 4];
        float4 o3 = *(const float4*)&P[2048 + ltid * 4];
        float2 r0 = unpk(acc0), r1 = unpk(acc1);
        Cs[(2 * nt) * 66 + 2 * mt]         = r0.x + o1.x + o2.x + o3.x;
        Cs[(2 * nt) * 66 + 2 * mt + 1]     = r0.y + o1.y + o2.y + o3.y;
        Cs[(2 * nt + 1) * 66 + 2 * mt]     = r1.x + o1.z + o2.z + o3.z;
        Cs[(2 * nt + 1) * 66 + 2 * mt + 1] = r1.y + o1.w + o2.w + o3.w;
    }
    __syncthreads();
    if (tid < 256) {
        int m = tid & 63, u = tid >> 6;
        int U = u0 + u;
        float gi = Cs[(u) * 66 + m]      + bih[U]        + bhh[U];
        float gf = Cs[(4 + u) * 66 + m]  + bih[512 + U]  + bhh[512 + U];
        float gg = Cs[(8 + u) * 66 + m]  + bih[1024 + U] + bhh[1024 + U];
        float go = Cs[(12 + u) * 66 + m] + bih[1536 + U] + bhh[1536 + U];
        float cc = sigf(gf) * g_c[m][U] + sigf(gi) * tanhf(gg);
        float hh = sigf(go) * tanhf(cc);
        g_c[m][U] = cc;
        __stcg(&g_h[nx][m][U], hh);
        Ps[u * 64 + m] = hh;
    }
    __syncthreads();
    if (tid < 64) {
        float h0 = Ps[tid], h1 = Ps[64 + tid], h2 = Ps[128 + tid], h3 = Ps[192 + tid];
        __stcg(&g_lnpart[jj][tid][0], h0 + h1 + h2 + h3);
        __stcg(&g_lnpart[jj][tid][1], h0 * h0 + h1 * h1 + h2 * h2 + h3 * h3);
    }
}

// phase B: heads GEMM, 4 cols/block, K split 4x128, LN(h) inline
__device__ void doHeads(int qc, int nx, float* scr,
                        const float* __restrict__ lnhg, const float* __restrict__ lnhb,
                        const float* __restrict__ Wrk, const float* __restrict__ Wwk,
                        const float* __restrict__ Wws, const float* __restrict__ Wer,
                        const float* __restrict__ Wad) {
    int tid = threadIdx.x;
    int q = tid >> 8, ltid = tid & 255;
    float* As = scr + q * 2240;      // [32][66]
    float* Ws = As + 2112;           // [32][4]
    float* smean = scr + 8960;       // 64
    float* srstd = scr + 9024;       // 64
    float* hacc = scr + 9088;        // 1024
    if (tid < 64) {
        float s = 0.f, s2 = 0.f;
#pragma unroll 8
        for (int j = 0; j < 128; ++j) {
            float2 lp = __ldcg((const float2*)&g_lnpart[j][tid][0]);
            s += lp.x; s2 += lp.y;
        }
        float m = s * (1.f / 512);
        smean[tid] = m;
        srstd[tid] = rsqrtf(s2 * (1.f / 512) - m * m + EPS);
    }
    __syncthreads();
    int m = ltid >> 2, c = ltid & 3;
    int ar0 = ltid >> 3, ar1 = ar0 + 32, ak = (ltid & 7) * 4;
    int kb = q * 128;
    const float* wp = headrow(qc * 4 + (ltid >> 3), Wrk, Wwk, Wws, Wer, Wad);  // ltid<32
    float acc = 0.f;
    float4 hv0, hv1, gv0, bv0, vwh = make_float4(0.f, 0.f, 0.f, 0.f);
    hv0 = __ldcg((const float4*)&g_h[nx][ar0][kb + ak]);
    hv1 = __ldcg((const float4*)&g_h[nx][ar1][kb + ak]);
    gv0 = *(const float4*)&lnhg[kb + ak];
    bv0 = *(const float4*)&lnhb[kb + ak];
    if (ltid < 32 && wp) vwh = *(const float4*)(wp + kb + ((ltid & 7) * 4));
    for (int kt = 0; kt < 128; kt += 32) {
        __syncthreads();
        {
            float mm = smean[ar0], rs = srstd[ar0];
            As[(ak + 0) * 66 + ar0] = (hv0.x - mm) * rs * gv0.x + bv0.x;
            As[(ak + 1) * 66 + ar0] = (hv0.y - mm) * rs * gv0.y + bv0.y;
            As[(ak + 2) * 66 + ar0] = (hv0.z - mm) * rs * gv0.z + bv0.z;
            As[(ak + 3) * 66 + ar0] = (hv0.w - mm) * rs * gv0.w + bv0.w;
            mm = smean[ar1]; rs = srstd[ar1];
            As[(ak + 0) * 66 + ar1] = (hv1.x - mm) * rs * gv0.x + bv0.x;
            As[(ak + 1) * 66 + ar1] = (hv1.y - mm) * rs * gv0.y + bv0.y;
            As[(ak + 2) * 66 + ar1] = (hv1.z - mm) * rs * gv0.z + bv0.z;
            As[(ak + 3) * 66 + ar1] = (hv1.w - mm) * rs * gv0.w + bv0.w;
        }
        if (ltid < 32) {
            int c2 = ltid >> 3, kq = (ltid & 7) * 4;
            Ws[(kq + 0) * 4 + c2] = vwh.x; Ws[(kq + 1) * 4 + c2] = vwh.y;
            Ws[(kq + 2) * 4 + c2] = vwh.z; Ws[(kq + 3) * 4 + c2] = vwh.w;
        }
        if (kt + 32 < 128) {
            hv0 = __ldcg((const float4*)&g_h[nx][ar0][kb + kt + 32 + ak]);
            hv1 = __ldcg((const float4*)&g_h[nx][ar1][kb + kt + 32 + ak]);
            gv0 = *(const float4*)&lnhg[kb + kt + 32 + ak];
            bv0 = *(const float4*)&lnhb[kb + kt + 32 + ak];
            if (ltid < 32 && wp) vwh = *(const float4*)(wp + kb + kt + 32 + ((ltid & 7) * 4));
        }
        __syncthreads();
#pragma unroll
        for (int k = 0; k < 32; ++k) acc += As[k * 66 + m] * Ws[k * 4 + c];
    }
    hacc[tid] = acc;
    __syncthreads();
    if (tid < 256)
        __stcg(&g_head[m][qc * 4 + c],
               hacc[tid] + hacc[tid + 256] + hacc[tid + 512] + hacc[tid + 768]);
}

// phase C (blocks 64..127): proj, 16 cols/block, K split 4x192
__device__ void doProj(int p, int trow, float* scr, const float* __restrict__ Aouts,
                       const float* __restrict__ Wproj, const float* __restrict__ bproj,
                       float* __restrict__ out) {
    int tid = threadIdx.x;
    int q = tid >> 8, ltid = tid & 255;
    float* As = scr + q * 2880;      // [32][68]
    float* Ws = As + 2176;           // [32][20]
    int r0 = (ltid >> 3) * 2, c0 = (ltid & 7) * 2;
    int ar0 = ltid >> 3, ar1 = ar0 + 32, ak = (ltid & 7) * 4;
    int wc = ltid >> 3, wk = (ltid & 7) * 4;
    int kb = q * 192;
    float a00 = 0.f, a01 = 0.f, a10 = 0.f, a11 = 0.f;
    float4 va0, va1, vw = make_float4(0.f, 0.f, 0.f, 0.f);
    va0 = __ldcg((const float4*)&Aouts[ar0 * 768 + kb + ak]);
    va1 = __ldcg((const float4*)&Aouts[ar1 * 768 + kb + ak]);
    if (ltid < 128) vw = *(const float4*)&Wproj[(size_t)(16 * p + wc) * 768 + kb + wk];
    for (int kt = 0; kt < 192; kt += 32) {
        __syncthreads();
        As[(ak + 0) * 68 + ar0] = va0.x; As[(ak + 1) * 68 + ar0] = va0.y;
        As[(ak + 2) * 68 + ar0] = va0.z; As[(ak + 3) * 68 + ar0] = va0.w;
        As[(ak + 0) * 68 + ar1] = va1.x; As[(ak + 1) * 68 + ar1] = va1.y;
        As[(ak + 2) * 68 + ar1] = va1.z; As[(ak + 3) * 68 + ar1] = va1.w;
        if (ltid < 128) {
            Ws[(wk + 0) * 20 + wc] = vw.x; Ws[(wk + 1) * 20 + wc] = vw.y;
            Ws[(wk + 2) * 20 + wc] = vw.z; Ws[(wk + 3) * 20 + wc] = vw.w;
        }
        if (kt + 32 < 192) {
            va0 = __ldcg((const float4*)&Aouts[ar0 * 768 + kb + kt + 32 + ak]);
            va1 = __ldcg((const float4*)&Aouts[ar1 * 768 + kb + kt + 32 + ak]);
            if (ltid < 128)
                vw = *(const float4*)&Wproj[(size_t)(16 * p + wc) * 768 + kb + kt + 32 + wk];
        }
        __syncthreads();
#pragma unroll
        for (int k = 0; k < 32; ++k) {
            float2 a = *(const float2*)&As[k * 68 + r0];
            float2 w = *(const float2*)&Ws[k * 20 + c0];
            a00 += a.x * w.x; a01 += a.x * w.y; a10 += a.y * w.x; a11 += a.y * w.y;
        }
    }
    __syncthreads();
    float* pacc = scr;  // 3072, reuse post-loop
    if (q > 0) *(float4*)&pacc[(q - 1) * 1024 + ltid * 4] = make_float4(a00, a01, a10, a11);
    __syncthreads();
    if (q == 0) {
        float4 o1 = *(const float4*)&pacc[ltid * 4];
        float4 o2 = *(const float4*)&pacc[1024 + ltid * 4];
        float4 o3 = *(const float4*)&pacc[2048 + ltid * 4];
        int col = 16 * p + c0;
        float b0 = bproj[col], b1 = bproj[col + 1];
        out[((size_t)(r0 + 0) * cL + trow) * cO + col]     = a00 + o1.x + o2.x + o3.x + b0;
        out[((size_t)(r0 + 0) * cL + trow) * cO + col + 1] = a01 + o1.y + o2.y + o3.y + b1;
        out[((size_t)(r0 + 1) * cL + trow) * cO + col]     = a10 + o1.z + o2.z + o3.z + b0;
        out[((size_t)(r0 + 1) * cL + trow) * cO + col + 1] = a11 + o1.w + o2.w + o3.w + b1;
    }
}

// phase C (blocks 0..63): memory write/read + outln + next ci (1024 threads)
__device__ void doMem(int t, int b, float* s_mem, float* scr, const float* __restrict__ x,
                      const float* __restrict__ brk, const float* __restrict__ bwk,
                      const float* __restrict__ bws, const float* __restrict__ ber,
                      const float* __restrict__ bad,
                      const float* __restrict__ lnhg, const float* __restrict__ lnhb,
                      const float* __restrict__ lnrkg, const float* __restrict__ lnrkb,
                      const float* __restrict__ lnwkg, const float* __restrict__ lnwkb,
                      const float* __restrict__ lnmg, const float* __restrict__ lnmb,
                      const float* __restrict__ lnog, const float* __restrict__ lnob,
                      const float* __restrict__ lning, const float* __restrict__ lninb) {
    float* s_hn = scr;           // 512
    float* s_rk = scr + 512;     // 256
    float* s_wk = scr + 768;     // 64
    float* s_er = scr + 832;     // 64
    float* s_ad = scr + 896;     // 64
    float* s_wkln = scr + 960;   // 64
    float* s_rkln = scr + 1024;  // 256
    float* s_wsc = scr + 1280;   // 256
    float* s_rsc = scr + 1536;   // 1024
    float* s_rv = scr + 2560;    // 256
    float* s_rvp = scr + 2816;   // 1024
    float* red = scr + 3840;     // 32
    float* misc = scr + 3872;    // 4
    int tid = threadIdx.x, warp = tid >> 5, lane = tid & 31;
    int nx = (t + 1) & 1, ob = t & 1;

    if (tid < 32) {
        float s = 0.f, s2 = 0.f;
#pragma unroll
        for (int j = 0; j < 4; ++j) {
            float2 lp = __ldcg((const float2*)&g_lnpart[lane * 4 + j][b][0]);
            s += lp.x; s2 += lp.y;
        }
#pragma unroll
        for (int o = 16; o; o >>= 1) {
            s += __shfl_xor_sync(0xffffffffu, s, o);
            s2 += __shfl_xor_sync(0xffffffffu, s2, o);
        }
        if (tid == 0) {
            float m = s * (1.f / 512);
            misc[1] = m;
            misc[2] = rsqrtf(s2 * (1.f / 512) - m * m + EPS);
        }
    }
    __syncthreads();
    float hm = misc[1], hrs = misc[2];
    if (tid < 512)
        s_hn[tid] = (__ldcg(&g_h[nx][b][tid]) - hm) * hrs * lnhg[tid] + lnhb[tid];
    if (tid < 449) {
        float v = __ldcg(&g_head[b][tid]);
        if (tid < 256) s_rk[tid] = v + brk[tid];
        else if (tid < 320) s_wk[tid - 256] = v + bwk[tid - 256];
        else if (tid == 320) misc[0] = sigf(v + bws[0]);
        else if (tid < 385) s_er[tid - 321] = sigf(v + ber[tid - 321]);
        else s_ad[tid - 385] = tanhf(v + bad[tid - 385]);
    }
    __syncthreads();
    if (warp == 0) {
        float x0 = s_wk[lane], x1 = s_wk[lane + 32], s = x0 + x1;
#pragma unroll
        for (int o = 16; o; o >>= 1) s += __shfl_xor_sync(0xffffffffu, s, o);
        float mean = s * (1.f / 64), d0 = x0 - mean, d1 = x1 - mean;
        float vs = d0 * d0 + d1 * d1;
#pragma unroll
        for (int o = 16; o; o >>= 1) vs += __shfl_xor_sync(0xffffffffu, vs, o);
        float rs = rsqrtf(vs * (1.f / 64) + EPS);
        s_wkln[lane] = d0 * rs * lnwkg[lane] + lnwkb[lane];
        s_wkln[lane + 32] = d1 * rs * lnwkg[lane + 32] + lnwkb[lane + 32];
    } else if (warp <= 4) {
        int r = warp - 1;
        float x0 = s_rk[r * 64 + lane], x1 = s_rk[r * 64 + lane + 32], s = x0 + x1;
#pragma unroll
        for (int o = 16; o; o >>= 1) s += __shfl_xor_sync(0xffffffffu, s, o);
        float mean = s * (1.f / 64), d0 = x0 - mean, d1 = x1 - mean;
        float vs = d0 * d0 + d1 * d1;
#pragma unroll
        for (int o = 16; o; o >>= 1) vs += __shfl_xor_sync(0xffffffffu, vs, o);
        float rs = rsqrtf(vs * (1.f / 64) + EPS);
        s_rkln[r * 64 + lane] = d0 * rs * lnrkg[lane] + lnrkb[lane];
        s_rkln[r * 64 + lane + 32] = d1 * rs * lnrkg[lane + 32] + lnrkb[lane + 32];
    }
    __syncthreads();
    float mg0 = lnmg[lane], mg1 = lnmg[lane + 32];
    float mb0 = lnmb[lane], mb1 = lnmb[lane + 32];
    float wkl0 = s_wkln[lane], wkl1 = s_wkln[lane + 32];
    for (int m = warp; m < cM; m += 32) {
        float x0 = s_mem[m * 64 + lane], x1 = s_mem[m * 64 + lane + 32], s = x0 + x1;
#pragma unroll
        for (int o = 16; o; o >>= 1) s += __shfl_xor_sync(0xffffffffu, s, o);
        float mean = s * (1.f / 64), d0 = x0 - mean, d1 = x1 - mean;
        float vs = d0 * d0 + d1 * d1;
#pragma unroll
        for (int o = 16; o; o >>= 1) vs += __shfl_xor_sync(0xffffffffu, vs, o);
        float rs = rsqrtf(vs * (1.f / 64) + EPS);
        float dot = (d0 * rs * mg0 + mb0) * wkl0 + (d1 * rs * mg1 + mb1) * wkl1;
#pragma unroll
        for (int o = 16; o; o >>= 1) dot += __shfl_xor_sync(0xffffffffu, dot, o);
        if (lane == 0) s_wsc[m] = dot;
    }
    __syncthreads();
    {
        float v = (tid < 256) ? s_wsc[tid] : -3e38f;
        float mx = brmax(v, red);
        float e = (tid < 256) ? expf(v - mx) : 0.f;
        float su = brsum(e, red);
        if (tid < 256) s_wsc[tid] = e / su * misc[0];
    }
    __syncthreads();
    for (int i = tid; i < cM * cHD; i += NTHR) {
        int m = i >> 6, hh = i & 63;
        float w = s_wsc[m];
        s_mem[i] = s_mem[i] * (1.f - w * s_er[hh]) + w * s_ad[hh];
    }
    __syncthreads();
    for (int m = warp; m < cM; m += 32) {
        float x0 = s_mem[m * 64 + lane], x1 = s_mem[m * 64 + lane + 32], s = x0 + x1;
#pragma unroll
        for (int o = 16; o; o >>= 1) s += __shfl_xor_sync(0xffffffffu, s, o);
        float mean = s * (1.f / 64), d0 = x0 - mean, d1 = x1 - mean;
        float vs = d0 * d0 + d1 * d1;
#pragma unroll
        for (int o = 16; o; o >>= 1) vs += __shfl_xor_sync(0xffffffffu, vs, o);
        float rs = rsqrtf(vs * (1.f / 64) + EPS);
        float n0 = d0 * rs * mg0 + mb0, n1 = d1 * rs * mg1 + mb1;
#pragma unroll
        for (int r = 0; r < 4; ++r) {
            float a = n0 * s_rkln[r * 64 + lane] + n1 * s_rkln[r * 64 + lane + 32];
#pragma unroll
            for (int o = 16; o; o >>= 1) a += __shfl_xor_sync(0xffffffffu, a, o);
            if (lane == 0) s_rsc[r * 256 + m] = a;
        }
    }
    __syncthreads();
#pragma unroll
    for (int r = 0; r < 4; ++r) {
        float v = (tid < 256) ? s_rsc[r * 256 + tid] : -3e38f;
        float mx = brmax(v, red);
        float e = (tid < 256) ? expf(v - mx) : 0.f;
        float su = brsum(e, red);
        if (tid < 256) s_rsc[r * 256 + tid] = e / su;
    }
    __syncthreads();
    {
        int r = tid >> 8, rest = tid & 255, hf = rest >> 6, hh = rest & 63;
        int mb = hf * 64;
        float a0 = 0.f, a1 = 0.f, a2 = 0.f, a3 = 0.f;
#pragma unroll 4
        for (int m = 0; m < 64; m += 4) {
            a0 += s_rsc[r * 256 + mb + m + 0] * s_mem[(mb + m + 0) * 64 + hh];
            a1 += s_rsc[r * 256 + mb + m + 1] * s_mem[(mb + m + 1) * 64 + hh];
            a2 += s_rsc[r * 256 + mb + m + 2] * s_mem[(mb + m + 2) * 64 + hh];
            a3 += s_rsc[r * 256 + mb + m + 3] * s_mem[(mb + m + 3) * 64 + hh];
        }
        s_rvp[tid] = (a0 + a1) + (a2 + a3);
    }
    __syncthreads();
    if (tid < 256) {
        int r = tid >> 6, hh = tid & 63;
        s_rv[tid] = (s_rvp[r * 256 + hh] + s_rvp[r * 256 + 64 + hh]) +
                    (s_rvp[r * 256 + 128 + hh] + s_rvp[r * 256 + 192 + hh]);
    }
    __syncthreads();
    {
        float o0 = (tid < 512) ? s_hn[tid] : 0.f;
        float o2 = (tid < 256) ? s_rv[tid] : 0.f;
        float mean = brsum(o0 + o2, red) * (1.f / cTO);
        float var;
        {
            float d0 = (tid < 512) ? (o0 - mean) : 0.f;
            float d2 = (tid < 256) ? (o2 - mean) : 0.f;
            var = brsum(d0 * d0 + d2 * d2, red) * (1.f / cTO);
        }
        float rs = rsqrtf(var + EPS);
        if (tid < 512)
            __stcg(&g_outln[ob][b][tid], (o0 - mean) * rs * lnog[tid] + lnob[tid]);
        if (tid < 256)
            __stcg(&g_outln[ob][b][512 + tid], (o2 - mean) * rs * lnog[512 + tid] + lnob[512 + tid]);
    }
    if (t + 1 < cL) {
        const float* xn = x + ((size_t)b * cL + t + 1) * cE;
        float a = (tid < 256) ? xn[tid] : ((tid < 512) ? s_rv[tid - 256] : 0.f);
        float mean = brsum(a, red) * (1.f / cCI);
        float d = (tid < 512) ? (a - mean) : 0.f;
        float var = brsum(d * d, red) * (1.f / cCI);
        float rs = rsqrtf(var + EPS);
        if (tid < 512) __stcg(&g_ci[b][tid], d * rs * lning[tid] + lninb[tid]);
    }
}

__global__ void __launch_bounds__(NTHR, 1) k_persist(
    const float* __restrict__ x, const float* __restrict__ Wih,
    const float* __restrict__ Whh, const float* __restrict__ bih,
    const float* __restrict__ bhh, const float* __restrict__ lning,
    const float* __restrict__ lninb, const float* __restrict__ lnhg,
    const float* __restrict__ lnhb, const float* __restrict__ Wrk,
    const float* __restrict__ brk, const float* __restrict__ Wwk,
    const float* __restrict__ bwk, const float* __restrict__ Wws,
    const float* __restrict__ bws, const float* __restrict__ Wer,
    const float* __restrict__ ber, const float* __restrict__ Wad,
    const float* __restrict__ bad, const float* __restrict__ lnrkg,
    const float* __restrict__ lnrkb, const float* __restrict__ lnwkg,
    const float* __restrict__ lnwkb, const float* __restrict__ lnmg,
    const float* __restrict__ lnmb, const float* __restrict__ lnog,
    const float* __restrict__ lnob, const float* __restrict__ Wproj,
    const float* __restrict__ bproj, float* __restrict__ out,
    float* __restrict__ memg, float* __restrict__ hout, float* __restrict__ cout) {
    extern __shared__ float sm[];
    float* s_mem = sm;          // 16384 (persistent memory, blocks 0..63)
    float* scr = sm + 16384;    // SCRF scratch
    int bx = blockIdx.x, tid = threadIdx.x;

    if (bx < 64) {
        for (int i = tid; i < cM * cHD; i += NTHR) s_mem[i] = 0.f;
        int b = bx;
        if (tid < 512) {
            g_c[b][tid] = 0.f;
            __stcg(&g_h[0][b][tid], 0.f);
        }
        float* red = scr;
        float a = (tid < 256) ? x[(size_t)b * cL * cE + tid] : 0.f;
        float mean = brsum(a, red) * (1.f / cCI);
        float d = (tid < 512) ? (a - mean) : 0.f;
        float var = brsum(d * d, red) * (1.f / cCI);
        float rs = rsqrtf(var + EPS);
        if (tid < 512) __stcg(&g_ci[b][tid], d * rs * lning[tid] + lninb[tid]);
    }
    gsync();

    for (int t = 0; t < cL; ++t) {
        doA(t, scr, Wih, Whh, bih, bhh);
        gsync();
        doHeads(bx, (t + 1) & 1, scr, lnhg, lnhb, Wrk, Wwk, Wws, Wer, Wad);
        gsync();
        if (bx < 64) {
            doMem(t, bx, s_mem, scr, x, brk, bwk, bws, ber, bad, lnhg, lnhb,
                  lnrkg, lnrkb, lnwkg, lnwkb, lnmg, lnmb, lnog, lnob, lning, lninb);
        } else if (t > 0) {
            doProj(bx - 64, t - 1, scr, &g_outln[(t - 1) & 1][0][0], Wproj, bproj, out);
        }
        gsync();
    }
    if (bx >= 64) {
        doProj(bx - 64, cL - 1, scr, &g_outln[(cL - 1) & 1][0][0], Wproj, bproj, out);
    } else {
        int b = bx;
        for (int i = tid; i < cM * cHD; i += NTHR) memg[(size_t)b * cM * cHD + i] = s_mem[i];
        if (tid < 512) {
            hout[b * cH + tid] = __ldcg(&g_h[0][b][tid]);
            cout[b * cH + tid] = __ldcg(&g_c[b][tid]);
        }
    }
}

extern "C" void kernel_launch(void* const* d_in, const int* in_sizes, int n_in,
                              void* d_out, int out_size) {
    const float** p = (const float**)d_in;
    float* out = (float*)d_out;
    float* memg = out + (size_t)cB * cL * cO;
    float* hout = memg + (size_t)cB * cM * cHD;
    float* cout = hout + (size_t)cB * cH;
    const int smem = (16384 + SCRF) * 4;
    cudaFuncSetAttribute(k_persist, cudaFuncAttributeMaxDynamicSharedMemorySize, smem);
    k_persist<<<NBLK, NTHR, smem>>>(p[0], p[1], p[2], p[3], p[4], p[5], p[6], p[7], p[8],
                                    p[9], p[10], p[11], p[12], p[13], p[14], p[15], p[16],
                                    p[17], p[18], p[19], p[20], p[21], p[22], p[23], p[24],
                                    p[25], p[26], p[27], p[28], out, memg, hout, cout);
}